// round 1
// baseline (speedup 1.0000x reference)
#include <cuda_runtime.h>
#include <cmath>

#define NB 128   // batch
#define NKE 64   // entities (K)
#define ND 128   // feature dim D
#define NS 128   // S
#define NL 2     // layers
#define MROWS (NB*NKE)   // 8192
#define SPITCH 132       // padded smem row stride (floats)

// ---------------- scratch (static device arrays; no allocation) ----------------
__device__ float g_x[MROWS*ND];
__device__ float g_q[MROWS*ND];
__device__ float g_k[MROWS*ND];
__device__ float g_P[MROWS*ND];
__device__ float g_Qm[MROWS*ND];
__device__ float g_u[MROWS*ND];
__device__ float g_h2[MROWS*ND];
__device__ float g_ln[MROWS*ND];
__device__ float g_mm[MROWS*ND];
__device__ float g_pool[NB*ND];
__device__ float g_proj[NB*NS];

__device__ __forceinline__ float gelu_exact(float x) {
    // exact gelu: x * Phi(x) = 0.5*x*(1+erf(x/sqrt(2)))
    return x * normcdff(x);
}

// ---------------- generic tiled SGEMM: C = act(alpha*A@(W[+W2]) + bias) [+ resid] ----
// A: MxK row-major, W: KxN row-major. Tile 64x64x16, 128 threads, 8x4 microtile.
// All dims must be multiples of tile sizes (true here: M in {8192,128}, N in {128}, K=128).
template<bool GELU, bool ADDW2, bool BIAS, bool RES>
__global__ void gemm_k(const float* __restrict__ A, const float* __restrict__ W,
                       const float* __restrict__ W2, const float* __restrict__ bias,
                       const float* __restrict__ resid, float* __restrict__ C,
                       int N, int K, float alpha)
{
    __shared__ float As[16][64];
    __shared__ float Bs[16][64];
    const int t  = threadIdx.x;
    const int bm = blockIdx.x * 64;
    const int bn = blockIdx.y * 64;
    const int ty = t >> 4;   // 0..7  (8 rows each)
    const int tx = t & 15;   // 0..15 (4 cols each)

    float acc[8][4];
#pragma unroll
    for (int i = 0; i < 8; i++)
#pragma unroll
        for (int j = 0; j < 4; j++) acc[i][j] = 0.f;

    for (int k0 = 0; k0 < K; k0 += 16) {
#pragma unroll
        for (int rep = 0; rep < 2; rep++) {
            int idx = t + rep * 128;
            int am  = idx >> 2;
            int ak  = (idx & 3) << 2;
            float4 av = *(const float4*)(A + (size_t)(bm + am) * K + k0 + ak);
            As[ak + 0][am] = av.x; As[ak + 1][am] = av.y;
            As[ak + 2][am] = av.z; As[ak + 3][am] = av.w;
            int bk  = idx >> 4;
            int bn4 = (idx & 15) << 2;
            float4 bv = *(const float4*)(W + (size_t)(k0 + bk) * N + bn + bn4);
            if (ADDW2) {
                float4 b2 = *(const float4*)(W2 + (size_t)(k0 + bk) * N + bn + bn4);
                bv.x += b2.x; bv.y += b2.y; bv.z += b2.z; bv.w += b2.w;
            }
            *(float4*)&Bs[bk][bn4] = bv;
        }
        __syncthreads();
#pragma unroll
        for (int kk = 0; kk < 16; kk++) {
            float a[8], b[4];
            *(float4*)&a[0] = *(const float4*)&As[kk][ty * 8];
            *(float4*)&a[4] = *(const float4*)&As[kk][ty * 8 + 4];
            *(float4*)&b[0] = *(const float4*)&Bs[kk][tx * 4];
#pragma unroll
            for (int i = 0; i < 8; i++)
#pragma unroll
                for (int j = 0; j < 4; j++) acc[i][j] += a[i] * b[j];
        }
        __syncthreads();
    }
#pragma unroll
    for (int i = 0; i < 8; i++) {
        int row = bm + ty * 8 + i;
        int col = bn + tx * 4;
        float vv[4];
#pragma unroll
        for (int j = 0; j < 4; j++) {
            float v = acc[i][j] * alpha;
            if (BIAS) v += bias[col + j];
            if (GELU) v = gelu_exact(v);
            vv[j] = v;
        }
        if (RES) {
            float4 r4 = *(const float4*)(resid + (size_t)row * N + col);
            vv[0] += r4.x; vv[1] += r4.y; vv[2] += r4.z; vv[3] += r4.w;
        }
        float4 o; o.x = vv[0]; o.y = vv[1]; o.z = vv[2]; o.w = vv[3];
        *(float4*)(C + (size_t)row * N + col) = o;
    }
}

// ---------------- fused attention + weighted-gelu-sum: one CTA per batch b -------
// logits = q@k^T, attn = softmax_j, u_i = sum_j attn_ij * gelu(P_i - Q_j + bv1)
__global__ void attn_u_kernel(const float* __restrict__ q, const float* __restrict__ k,
                              const float* __restrict__ P, const float* __restrict__ Q,
                              const float* __restrict__ bv1, float* __restrict__ u)
{
    extern __shared__ float sm[];
    float* sq = sm;
    float* sk = sq + NKE * SPITCH;
    float* sP = sk + NKE * SPITCH;
    float* sQ = sP + NKE * SPITCH;
    float* sa = sQ + NKE * SPITCH;   // 64*64 logits/attn

    const int t = threadIdx.x;       // 512 threads
    const int b = blockIdx.x;
    const size_t base = (size_t)b * NKE * ND;

    // load q,k,P,Q tiles into padded smem
    {
        const float* srcs[4] = {q + base, k + base, P + base, Q + base};
        float* dsts[4] = {sq, sk, sP, sQ};
#pragma unroll
        for (int a = 0; a < 4; a++) {
            const float4* s = (const float4*)srcs[a];
            for (int idx = t; idx < NKE * ND / 4; idx += 512) {
                float4 v = s[idx];
                int row = idx >> 5;          // 32 float4 per row
                int col = (idx & 31) << 2;
                *(float4*)&dsts[a][row * SPITCH + col] = v;
            }
        }
    }
    __syncthreads();

    // logits: thread t computes 8 logits for row i = t>>3, j = (t&7) + jj*8
    {
        const int i  = t >> 3;
        const int jb = t & 7;
        float acc[8] = {0, 0, 0, 0, 0, 0, 0, 0};
        const float* qrow = sq + i * SPITCH;
        for (int d = 0; d < ND; d += 4) {
            float4 qv = *(const float4*)(qrow + d);
#pragma unroll
            for (int jj = 0; jj < 8; jj++) {
                float4 kv = *(const float4*)(sk + (jb + jj * 8) * SPITCH + d);
                acc[jj] += qv.x * kv.x + qv.y * kv.y + qv.z * kv.z + qv.w * kv.w;
            }
        }
#pragma unroll
        for (int jj = 0; jj < 8; jj++) sa[i * 64 + jb + jj * 8] = acc[jj];
    }
    __syncthreads();

    // softmax over j: warp w handles rows w*4 .. w*4+3
    {
        const int w = t >> 5, lane = t & 31;
#pragma unroll
        for (int r = 0; r < 4; r++) {
            int i = w * 4 + r;
            float v0 = sa[i * 64 + lane], v1 = sa[i * 64 + lane + 32];
            float mx = fmaxf(v0, v1);
            for (int o = 16; o; o >>= 1) mx = fmaxf(mx, __shfl_xor_sync(0xffffffffu, mx, o));
            float e0 = __expf(v0 - mx), e1 = __expf(v1 - mx);
            float s = e0 + e1;
            for (int o = 16; o; o >>= 1) s += __shfl_xor_sync(0xffffffffu, s, o);
            float inv = 1.0f / s;
            sa[i * 64 + lane] = e0 * inv;
            sa[i * 64 + lane + 32] = e1 * inv;
        }
    }
    __syncthreads();

    // u: warp w, lane covers d = lane*4..+3 (float4); i = w + ii*16
    {
        const int w = t >> 5, lane = t & 31;
        const int dl = lane << 2;
        float4 bv = *(const float4*)(bv1 + dl);
#pragma unroll
        for (int ii = 0; ii < 4; ii++) {
            int i = w + ii * 16;
            float4 p = *(const float4*)(sP + i * SPITCH + dl);
            float p0 = p.x + bv.x, p1 = p.y + bv.y, p2 = p.z + bv.z, p3 = p.w + bv.w;
            float a0 = 0, a1 = 0, a2 = 0, a3 = 0;
            for (int j = 0; j < NKE; j++) {
                float att = sa[i * 64 + j];
                float4 qq = *(const float4*)(sQ + j * SPITCH + dl);
                a0 += att * gelu_exact(p0 - qq.x);
                a1 += att * gelu_exact(p1 - qq.y);
                a2 += att * gelu_exact(p2 - qq.z);
                a3 += att * gelu_exact(p3 - qq.w);
            }
            float4 o; o.x = a0; o.y = a1; o.z = a2; o.w = a3;
            *(float4*)(u + base + (size_t)i * ND + dl) = o;
        }
    }
}

// ---------------- layernorm (warp per row of 128) -------------------------------
__global__ void ln_kernel(const float* __restrict__ in, const float* __restrict__ g,
                          const float* __restrict__ bta, float* __restrict__ out)
{
    int row  = blockIdx.x * 8 + (threadIdx.x >> 5);
    int lane = threadIdx.x & 31;
    const float4 v = *(const float4*)(in + (size_t)row * ND + lane * 4);
    float s  = v.x + v.y + v.z + v.w;
    float s2 = v.x * v.x + v.y * v.y + v.z * v.z + v.w * v.w;
    for (int o = 16; o; o >>= 1) {
        s  += __shfl_xor_sync(0xffffffffu, s, o);
        s2 += __shfl_xor_sync(0xffffffffu, s2, o);
    }
    float mu  = s * (1.0f / ND);
    float var = s2 * (1.0f / ND) - mu * mu;
    float inv = rsqrtf(var + 1e-5f);
    float4 gg = *(const float4*)(g + lane * 4);
    float4 bb = *(const float4*)(bta + lane * 4);
    float4 o;
    o.x = (v.x - mu) * inv * gg.x + bb.x;
    o.y = (v.y - mu) * inv * gg.y + bb.y;
    o.z = (v.z - mu) * inv * gg.z + bb.z;
    o.w = (v.w - mu) * inv * gg.w + bb.w;
    *(float4*)(out + (size_t)row * ND + lane * 4) = o;
}

__global__ void pool_kernel(const float* __restrict__ x, float* __restrict__ pooled)
{
    int b = blockIdx.x, d = threadIdx.x;
    float s = 0.f;
    const float* p = x + (size_t)b * NKE * ND + d;
    for (int i = 0; i < NKE; i++) s += p[i * ND];
    pooled[b * ND + d] = s;
}

__global__ void copy_kernel(const float* __restrict__ src, float* __restrict__ dst, int n4)
{
    int i = blockIdx.x * blockDim.x + threadIdx.x;
    if (i < n4) ((float4*)dst)[i] = ((const float4*)src)[i];
}

// ---------------- launch --------------------------------------------------------
extern "C" void kernel_launch(void* const* d_in, const int* in_sizes, int n_in,
                              void* d_out, int out_size)
{
    const float* x_in = (const float*)d_in[0];
    const float* Wk   = (const float*)d_in[1];
    const float* Wq   = (const float*)d_in[2];
    const float* Wv1  = (const float*)d_in[3];
    const float* bv1  = (const float*)d_in[4];
    const float* Wv2  = (const float*)d_in[5];
    const float* bv2  = (const float*)d_in[6];
    const float* lng  = (const float*)d_in[7];
    const float* lnb  = (const float*)d_in[8];
    const float* Wm1  = (const float*)d_in[9];
    const float* bm1  = (const float*)d_in[10];
    const float* Wm2  = (const float*)d_in[11];
    const float* bm2  = (const float*)d_in[12];
    const float* Wp   = (const float*)d_in[13];
    const float* bp   = (const float*)d_in[14];
    const float* Wmu  = (const float*)d_in[15];
    const float* bmu  = (const float*)d_in[16];
    const float* Wsp  = (const float*)d_in[17];
    const float* bsp  = (const float*)d_in[18];
    float* out = (float*)d_out;

    float *px, *pq, *pk, *pP, *pQ, *pu, *ph2, *pln, *pm, *ppool, *pproj;
    cudaGetSymbolAddress((void**)&px, g_x);
    cudaGetSymbolAddress((void**)&pq, g_q);
    cudaGetSymbolAddress((void**)&pk, g_k);
    cudaGetSymbolAddress((void**)&pP, g_P);
    cudaGetSymbolAddress((void**)&pQ, g_Qm);
    cudaGetSymbolAddress((void**)&pu, g_u);
    cudaGetSymbolAddress((void**)&ph2, g_h2);
    cudaGetSymbolAddress((void**)&pln, g_ln);
    cudaGetSymbolAddress((void**)&pm, g_mm);
    cudaGetSymbolAddress((void**)&ppool, g_pool);
    cudaGetSymbolAddress((void**)&pproj, g_proj);

    const int SMEM_AU = (4 * NKE * SPITCH + NKE * NKE) * (int)sizeof(float);
    cudaFuncSetAttribute(attn_u_kernel, cudaFuncAttributeMaxDynamicSharedMemorySize, SMEM_AU);

    const float scale = 1.0f / sqrtf((float)ND);

    copy_kernel<<<(MROWS * ND / 4 + 255) / 256, 256>>>(x_in, px, MROWS * ND / 4);

    dim3 gg(MROWS / 64, ND / 64);   // (128, 2)
    for (int l = 0; l < NL; l++) {
        const float* Wk_l  = Wk  + (size_t)l * ND * ND;
        const float* Wq_l  = Wq  + (size_t)l * ND * ND;
        const float* Wv1t  = Wv1 + (size_t)l * 2 * ND * ND;   // rows 0..D-1   (xi part)
        const float* Wv1b  = Wv1t + (size_t)ND * ND;          // rows D..2D-1  (r part)
        const float* bv1_l = bv1 + (size_t)l * ND;
        const float* Wv2_l = Wv2 + (size_t)l * ND * ND;
        const float* bv2_l = bv2 + (size_t)l * ND;
        const float* g_l   = lng + (size_t)l * ND;
        const float* b_l   = lnb + (size_t)l * ND;
        const float* Wm1_l = Wm1 + (size_t)l * ND * ND;
        const float* bm1_l = bm1 + (size_t)l * ND;
        const float* Wm2_l = Wm2 + (size_t)l * ND * ND;
        const float* bm2_l = bm2 + (size_t)l * ND;

        // q = x@Wq * scale ; k = x@Wk ; P = x@(Wtop+Wbot) ; Q = x@Wbot
        gemm_k<false, false, false, false><<<gg, 128>>>(px, Wq_l, nullptr, nullptr, nullptr, pq, ND, ND, scale);
        gemm_k<false, false, false, false><<<gg, 128>>>(px, Wk_l, nullptr, nullptr, nullptr, pk, ND, ND, 1.f);
        gemm_k<false, true,  false, false><<<gg, 128>>>(px, Wv1t, Wv1b,   nullptr, nullptr, pP, ND, ND, 1.f);
        gemm_k<false, false, false, false><<<gg, 128>>>(px, Wv1b, nullptr, nullptr, nullptr, pQ, ND, ND, 1.f);

        attn_u_kernel<<<NB, 512, SMEM_AU>>>(pq, pk, pP, pQ, bv1_l, pu);

        // h2 = x + u@Wv2 + bv2
        gemm_k<false, false, true, true><<<gg, 128>>>(pu, Wv2_l, nullptr, bv2_l, px, ph2, ND, ND, 1.f);
        // mlp_in = LN(h2)
        ln_kernel<<<MROWS / 8, 256>>>(ph2, g_l, b_l, pln);
        // m = gelu(mlp_in@Wm1 + bm1)
        gemm_k<true, false, true, false><<<gg, 128>>>(pln, Wm1_l, nullptr, bm1_l, nullptr, pm, ND, ND, 1.f);
        // x = x + m@Wm2 + bm2   (in-place residual)
        gemm_k<false, false, true, true><<<gg, 128>>>(pm, Wm2_l, nullptr, bm2_l, px, px, ND, ND, 1.f);
    }

    pool_kernel<<<NB, ND>>>(px, ppool);

    dim3 gh(NB / 64, NS / 64);  // (2, 2)
    gemm_k<true,  false, true, false><<<gh, 128>>>(ppool, Wp,  nullptr, bp,  nullptr, pproj, NS, ND, 1.f);
    gemm_k<false, false, true, false><<<gh, 128>>>(pproj, Wmu, nullptr, bmu, nullptr, out,            NS, NS, 1.f);
    gemm_k<false, false, true, false><<<gh, 128>>>(pproj, Wsp, nullptr, bsp, nullptr, out + NB * NS,  NS, NS, 1.f);
}

// round 2
// speedup vs baseline: 1.4359x; 1.4359x over previous
#include <cuda_runtime.h>
#include <cmath>

#define NB 128   // batch
#define NKE 64   // entities (K)
#define ND 128   // feature dim D
#define NS 128   // S
#define NL 2     // layers
#define MROWS (NB*NKE)   // 8192
#define SPITCH 132       // padded smem row stride (floats)
#define NCAT 512         // fused q|k|P|Q width

// ---------------- scratch (static device arrays; no allocation) ----------------
__device__ float g_x[MROWS*ND];
__device__ float g_qkpq[MROWS*NCAT];          // 16 MB
__device__ float g_u[MROWS*ND];
__device__ float g_h2[MROWS*ND];
__device__ float g_ln[MROWS*ND];
__device__ float g_mm[MROWS*ND];
__device__ float g_wcat[NL*ND*NCAT];          // per-layer fused weights

__device__ __forceinline__ float gelu_fast(float x) {
    // gelu(x) = 0.5*x*(1 + erf(x/sqrt(2))), erf via A&S 7.1.26 (|err| <= 1.5e-7)
    float z = fabsf(x) * 0.70710678118654752f;
    float t = __frcp_rn(fmaf(0.3275911f, z, 1.0f));
    float p = fmaf(1.061405429f, t, -1.453152027f);
    p = fmaf(p, t, 1.421413741f);
    p = fmaf(p, t, -0.284496736f);
    p = fmaf(p, t, 0.254829592f);
    p = p * t;
    float e = __expf(-z * z);
    float erfv = fmaf(-p, e, 1.0f);           // erf(|x|/sqrt2)
    float s = copysignf(erfv, x);
    return 0.5f * x * (1.0f + s);
}

// ---------------- weight-prep: Wcat[l] = [Wq*scale | Wk | Wtop+Wbot | Wbot] ------
__global__ void prep_wcat(const float* __restrict__ Wq, const float* __restrict__ Wk,
                          const float* __restrict__ Wv1, float* __restrict__ Wcat,
                          float scale)
{
    int l   = blockIdx.y;
    int idx = blockIdx.x * 256 + threadIdx.x;      // 0..65535
    int row = idx >> 9;                             // 0..127
    int col = idx & 511;
    int c   = col & 127;
    const float* Wq_l  = Wq  + (size_t)l * ND * ND;
    const float* Wk_l  = Wk  + (size_t)l * ND * ND;
    const float* Wtop  = Wv1 + (size_t)l * 2 * ND * ND;
    const float* Wbot  = Wtop + (size_t)ND * ND;
    float v;
    switch (col >> 7) {
        case 0:  v = Wq_l[row * ND + c] * scale;                  break;
        case 1:  v = Wk_l[row * ND + c];                          break;
        case 2:  v = Wtop[row * ND + c] + Wbot[row * ND + c];     break;
        default: v = Wbot[row * ND + c];                          break;
    }
    Wcat[(size_t)l * ND * NCAT + idx] = v;
}

// ---------------- tiled SGEMM: C = act(A@W + bias) [+ resid] --------------------
// A: MxK row-major, W: KxN row-major. Tile TMx64x16, 128 threads.
template<int TM, bool GELU, bool BIAS, bool RES>
__global__ void gemm_k(const float* __restrict__ A, const float* __restrict__ W,
                       const float* __restrict__ bias,
                       const float* __restrict__ resid, float* __restrict__ C,
                       int N, int K, int CSTRIDE)
{
    __shared__ float As[16][TM];
    __shared__ float Bs[16][64];
    constexpr int R = TM / 8;                  // rows per thread (8 or 4)
    const int t  = threadIdx.x;
    const int bm = blockIdx.x * TM;
    const int bn = blockIdx.y * 64;
    const int ty = t >> 4;                     // 0..7
    const int tx = t & 15;                     // 0..15

    float acc[R][4];
#pragma unroll
    for (int i = 0; i < R; i++)
#pragma unroll
        for (int j = 0; j < 4; j++) acc[i][j] = 0.f;

    for (int k0 = 0; k0 < K; k0 += 16) {
#pragma unroll
        for (int rep = 0; rep < TM / 32; rep++) {
            int idx = t + rep * 128;
            int am  = idx >> 2;
            int ak  = (idx & 3) << 2;
            float4 av = *(const float4*)(A + (size_t)(bm + am) * K + k0 + ak);
            As[ak + 0][am] = av.x; As[ak + 1][am] = av.y;
            As[ak + 2][am] = av.z; As[ak + 3][am] = av.w;
        }
#pragma unroll
        for (int rep = 0; rep < 2; rep++) {
            int idx = t + rep * 128;
            int bk  = idx >> 4;
            int bn4 = (idx & 15) << 2;
            float4 bv = *(const float4*)(W + (size_t)(k0 + bk) * N + bn + bn4);
            *(float4*)&Bs[bk][bn4] = bv;
        }
        __syncthreads();
#pragma unroll
        for (int kk = 0; kk < 16; kk++) {
            float a[R], b[4];
#pragma unroll
            for (int i = 0; i < R; i += 4)
                *(float4*)&a[i] = *(const float4*)&As[kk][ty * R + i];
            *(float4*)&b[0] = *(const float4*)&Bs[kk][tx * 4];
#pragma unroll
            for (int i = 0; i < R; i++)
#pragma unroll
                for (int j = 0; j < 4; j++) acc[i][j] += a[i] * b[j];
        }
        __syncthreads();
    }
#pragma unroll
    for (int i = 0; i < R; i++) {
        int row = bm + ty * R + i;
        int col = bn + tx * 4;
        float vv[4];
#pragma unroll
        for (int j = 0; j < 4; j++) {
            float v = acc[i][j];
            if (BIAS) v += bias[col + j];
            if (GELU) v = gelu_fast(v);
            vv[j] = v;
        }
        if (RES) {
            float4 r4 = *(const float4*)(resid + (size_t)row * CSTRIDE + col);
            vv[0] += r4.x; vv[1] += r4.y; vv[2] += r4.z; vv[3] += r4.w;
        }
        float4 o; o.x = vv[0]; o.y = vv[1]; o.z = vv[2]; o.w = vv[3];
        *(float4*)(C + (size_t)row * CSTRIDE + col) = o;
    }
}

// ---------------- fused attention + weighted-gelu-sum: one CTA per batch b -------
// qkpq rows have stride NCAT: [q | k | P | Q]
__global__ void attn_u_kernel(const float* __restrict__ qkpq,
                              const float* __restrict__ bv1, float* __restrict__ u)
{
    extern __shared__ float sm[];
    float* sq = sm;
    float* sk = sq + NKE * SPITCH;
    float* sP = sk + NKE * SPITCH;
    float* sQ = sP + NKE * SPITCH;
    float* sa = sQ + NKE * SPITCH;   // 64*64 logits/attn

    const int t = threadIdx.x;       // 512 threads
    const int b = blockIdx.x;
    const size_t base = (size_t)b * NKE;

    // load q,k,P,Q tiles into padded smem
    {
        float* dsts[4] = {sq, sk, sP, sQ};
#pragma unroll
        for (int a = 0; a < 4; a++) {
            const float* src = qkpq + base * NCAT + a * ND;
            for (int idx = t; idx < NKE * ND / 4; idx += 512) {
                int row = idx >> 5;          // 32 float4 per row
                int col = (idx & 31) << 2;
                float4 v = *(const float4*)(src + (size_t)row * NCAT + col);
                *(float4*)&dsts[a][row * SPITCH + col] = v;
            }
        }
    }
    __syncthreads();

    // logits: thread t computes 8 logits for row i = t>>3, j = (t&7) + jj*8
    {
        const int i  = t >> 3;
        const int jb = t & 7;
        float acc[8] = {0, 0, 0, 0, 0, 0, 0, 0};
        const float* qrow = sq + i * SPITCH;
        for (int d = 0; d < ND; d += 4) {
            float4 qv = *(const float4*)(qrow + d);
#pragma unroll
            for (int jj = 0; jj < 8; jj++) {
                float4 kv = *(const float4*)(sk + (jb + jj * 8) * SPITCH + d);
                acc[jj] += qv.x * kv.x + qv.y * kv.y + qv.z * kv.z + qv.w * kv.w;
            }
        }
#pragma unroll
        for (int jj = 0; jj < 8; jj++) sa[i * 64 + jb + jj * 8] = acc[jj];
    }
    __syncthreads();

    // softmax over j: warp w handles rows w*4 .. w*4+3
    {
        const int w = t >> 5, lane = t & 31;
#pragma unroll
        for (int r = 0; r < 4; r++) {
            int i = w * 4 + r;
            float v0 = sa[i * 64 + lane], v1 = sa[i * 64 + lane + 32];
            float mx = fmaxf(v0, v1);
            for (int o = 16; o; o >>= 1) mx = fmaxf(mx, __shfl_xor_sync(0xffffffffu, mx, o));
            float e0 = __expf(v0 - mx), e1 = __expf(v1 - mx);
            float s = e0 + e1;
            for (int o = 16; o; o >>= 1) s += __shfl_xor_sync(0xffffffffu, s, o);
            float inv = 1.0f / s;
            sa[i * 64 + lane] = e0 * inv;
            sa[i * 64 + lane + 32] = e1 * inv;
        }
    }
    __syncthreads();

    // u: warp w, lane covers d = lane*4..+3 (float4); i = w + ii*16
    {
        const int w = t >> 5, lane = t & 31;
        const int dl = lane << 2;
        float4 bv = *(const float4*)(bv1 + dl);
#pragma unroll
        for (int ii = 0; ii < 4; ii++) {
            int i = w + ii * 16;
            float4 p = *(const float4*)(sP + i * SPITCH + dl);
            float p0 = p.x + bv.x, p1 = p.y + bv.y, p2 = p.z + bv.z, p3 = p.w + bv.w;
            float a0 = 0, a1 = 0, a2 = 0, a3 = 0;
            for (int j = 0; j < NKE; j++) {
                float att = sa[i * 64 + j];
                float4 qq = *(const float4*)(sQ + j * SPITCH + dl);
                a0 += att * gelu_fast(p0 - qq.x);
                a1 += att * gelu_fast(p1 - qq.y);
                a2 += att * gelu_fast(p2 - qq.z);
                a3 += att * gelu_fast(p3 - qq.w);
            }
            float4 o; o.x = a0; o.y = a1; o.z = a2; o.w = a3;
            *(float4*)(u + (base + i) * ND + dl) = o;
        }
    }
}

// ---------------- layernorm (warp per row of 128) -------------------------------
__global__ void ln_kernel(const float* __restrict__ in, const float* __restrict__ g,
                          const float* __restrict__ bta, float* __restrict__ out)
{
    int row  = blockIdx.x * 8 + (threadIdx.x >> 5);
    int lane = threadIdx.x & 31;
    const float4 v = *(const float4*)(in + (size_t)row * ND + lane * 4);
    float s  = v.x + v.y + v.z + v.w;
    float s2 = v.x * v.x + v.y * v.y + v.z * v.z + v.w * v.w;
    for (int o = 16; o; o >>= 1) {
        s  += __shfl_xor_sync(0xffffffffu, s, o);
        s2 += __shfl_xor_sync(0xffffffffu, s2, o);
    }
    float mu  = s * (1.0f / ND);
    float var = s2 * (1.0f / ND) - mu * mu;
    float inv = rsqrtf(var + 1e-5f);
    float4 gg = *(const float4*)(g + lane * 4);
    float4 bb = *(const float4*)(bta + lane * 4);
    float4 o;
    o.x = (v.x - mu) * inv * gg.x + bb.x;
    o.y = (v.y - mu) * inv * gg.y + bb.y;
    o.z = (v.z - mu) * inv * gg.z + bb.z;
    o.w = (v.w - mu) * inv * gg.w + bb.w;
    *(float4*)(out + (size_t)row * ND + lane * 4) = o;
}

// ---------------- fused head: pool + proj(gelu) + mu/sp projections -------------
__global__ void head_kernel(const float* __restrict__ x,
                            const float* __restrict__ Wp,  const float* __restrict__ bp,
                            const float* __restrict__ Wmu, const float* __restrict__ bmu,
                            const float* __restrict__ Wsp, const float* __restrict__ bsp,
                            float* __restrict__ out)
{
    __shared__ float spool[ND];
    __shared__ float sproj[NS];
    const int b = blockIdx.x;
    const int t = threadIdx.x;   // 128 threads

    // pool over entities
    {
        float s = 0.f;
        const float* p = x + (size_t)b * NKE * ND + t;
        for (int i = 0; i < NKE; i++) s += p[i * ND];
        spool[t] = s;
    }
    __syncthreads();

    // proj = gelu(pooled @ Wp + bp)
    {
        float acc = bp[t];
        for (int d = 0; d < ND; d++) acc += spool[d] * Wp[d * NS + t];
        sproj[t] = gelu_fast(acc);
    }
    __syncthreads();

    // mu/sp
    {
        float amu = bmu[t], asp = bsp[t];
        for (int s = 0; s < NS; s++) {
            float f = sproj[s];
            amu += f * Wmu[s * NS + t];
            asp += f * Wsp[s * NS + t];
        }
        out[(size_t)b * NS + t] = amu;
        out[(size_t)NB * NS + (size_t)b * NS + t] = asp;
    }
}

__global__ void copy_kernel(const float* __restrict__ src, float* __restrict__ dst, int n4)
{
    int i = blockIdx.x * blockDim.x + threadIdx.x;
    if (i < n4) ((float4*)dst)[i] = ((const float4*)src)[i];
}

// ---------------- launch --------------------------------------------------------
extern "C" void kernel_launch(void* const* d_in, const int* in_sizes, int n_in,
                              void* d_out, int out_size)
{
    const float* x_in = (const float*)d_in[0];
    const float* Wk   = (const float*)d_in[1];
    const float* Wq   = (const float*)d_in[2];
    const float* Wv1  = (const float*)d_in[3];
    const float* bv1  = (const float*)d_in[4];
    const float* Wv2  = (const float*)d_in[5];
    const float* bv2  = (const float*)d_in[6];
    const float* lng  = (const float*)d_in[7];
    const float* lnb  = (const float*)d_in[8];
    const float* Wm1  = (const float*)d_in[9];
    const float* bm1  = (const float*)d_in[10];
    const float* Wm2  = (const float*)d_in[11];
    const float* bm2  = (const float*)d_in[12];
    const float* Wp   = (const float*)d_in[13];
    const float* bp   = (const float*)d_in[14];
    const float* Wmu  = (const float*)d_in[15];
    const float* bmu  = (const float*)d_in[16];
    const float* Wsp  = (const float*)d_in[17];
    const float* bsp  = (const float*)d_in[18];
    float* out = (float*)d_out;

    float *px, *pqkpq, *pu, *ph2, *pln, *pm, *pwcat;
    cudaGetSymbolAddress((void**)&px,    g_x);
    cudaGetSymbolAddress((void**)&pqkpq, g_qkpq);
    cudaGetSymbolAddress((void**)&pu,    g_u);
    cudaGetSymbolAddress((void**)&ph2,   g_h2);
    cudaGetSymbolAddress((void**)&pln,   g_ln);
    cudaGetSymbolAddress((void**)&pm,    g_mm);
    cudaGetSymbolAddress((void**)&pwcat, g_wcat);

    const int SMEM_AU = (4 * NKE * SPITCH + NKE * NKE) * (int)sizeof(float);
    cudaFuncSetAttribute(attn_u_kernel, cudaFuncAttributeMaxDynamicSharedMemorySize, SMEM_AU);

    const float scale = 1.0f / sqrtf((float)ND);

    copy_kernel<<<(MROWS * ND / 4 + 255) / 256, 256>>>(x_in, px, MROWS * ND / 4);
    prep_wcat<<<dim3(256, NL), 256>>>(Wq, Wk, Wv1, pwcat, scale);

    dim3 gcat(MROWS / 64, NCAT / 64);   // (128, 8) = 1024 CTAs
    dim3 g32(MROWS / 32, ND / 64);      // (256, 2) = 512 CTAs
    for (int l = 0; l < NL; l++) {
        const float* Wcat_l = pwcat + (size_t)l * ND * NCAT;
        const float* bv1_l = bv1 + (size_t)l * ND;
        const float* Wv2_l = Wv2 + (size_t)l * ND * ND;
        const float* bv2_l = bv2 + (size_t)l * ND;
        const float* g_l   = lng + (size_t)l * ND;
        const float* b_l   = lnb + (size_t)l * ND;
        const float* Wm1_l = Wm1 + (size_t)l * ND * ND;
        const float* bm1_l = bm1 + (size_t)l * ND;
        const float* Wm2_l = Wm2 + (size_t)l * ND * ND;
        const float* bm2_l = bm2 + (size_t)l * ND;

        // [q|k|P|Q] = x @ Wcat
        gemm_k<64, false, false, false><<<gcat, 128>>>(px, Wcat_l, nullptr, nullptr, pqkpq, NCAT, ND, NCAT);

        attn_u_kernel<<<NB, 512, SMEM_AU>>>(pqkpq, bv1_l, pu);

        // h2 = x + u@Wv2 + bv2
        gemm_k<32, false, true, true><<<g32, 128>>>(pu, Wv2_l, bv2_l, px, ph2, ND, ND, ND);
        // mlp_in = LN(h2)
        ln_kernel<<<MROWS / 8, 256>>>(ph2, g_l, b_l, pln);
        // m = gelu(mlp_in@Wm1 + bm1)
        gemm_k<32, true, true, false><<<g32, 128>>>(pln, Wm1_l, bm1_l, nullptr, pm, ND, ND, ND);
        // x = x + m@Wm2 + bm2   (in-place residual)
        gemm_k<32, false, true, true><<<g32, 128>>>(pm, Wm2_l, bm2_l, px, px, ND, ND, ND);
    }

    head_kernel<<<NB, ND>>>(px, Wp, bp, Wmu, bmu, Wsp, bsp, out);
}

// round 4
// speedup vs baseline: 1.6333x; 1.1375x over previous
#include <cuda_runtime.h>
#include <cmath>

#define NB 128   // batch
#define NKE 64   // entities (K)
#define ND 128   // feature dim D
#define NS 128   // S
#define NL 2     // layers
#define MROWS (NB*NKE)   // 8192
#define SPITCH 132       // padded smem row stride (floats)
#define NCAT 512         // fused q|k|P|Q width

// ---------------- scratch (static device arrays; no allocation) ----------------
__device__ float g_x[MROWS*ND];
__device__ float g_qkpq[MROWS*NCAT];          // 16 MB
__device__ float g_u[MROWS*ND];
__device__ float g_h2[MROWS*ND];
__device__ float g_ln[MROWS*ND];
__device__ float g_mm[MROWS*ND];
__device__ float g_wcat[NL*ND*NCAT];          // per-layer fused weights

__device__ __forceinline__ float gelu_fast(float x) {
    // gelu(x) = 0.5*x*(1 + erf(x/sqrt(2))), erf via A&S 7.1.25 (|err| <= 2.5e-5)
    float z = fabsf(x) * 0.70710678118654752f;
    float t = __frcp_rn(fmaf(0.47047f, z, 1.0f));
    float p = fmaf(fmaf(0.7478556f, t, -0.0958798f), t, 0.3480242f) * t;
    float e = __expf(-z * z);
    float erfv = fmaf(-p, e, 1.0f);
    float s = copysignf(erfv, x);
    float hx = 0.5f * x;
    return fmaf(hx, s, hx);
}

// ---------------- weight-prep: Wcat[l] = [Wq*scale | Wk | Wtop+Wbot | Wbot] ------
__global__ void prep_wcat(const float* __restrict__ Wq, const float* __restrict__ Wk,
                          const float* __restrict__ Wv1, float* __restrict__ Wcat,
                          float scale)
{
    int l   = blockIdx.y;
    int idx = blockIdx.x * 256 + threadIdx.x;      // 0..65535
    int row = idx >> 9;                             // 0..127
    int col = idx & 511;
    int c   = col & 127;
    const float* Wq_l  = Wq  + (size_t)l * ND * ND;
    const float* Wk_l  = Wk  + (size_t)l * ND * ND;
    const float* Wtop  = Wv1 + (size_t)l * 2 * ND * ND;
    const float* Wbot  = Wtop + (size_t)ND * ND;
    float v;
    switch (col >> 7) {
        case 0:  v = Wq_l[row * ND + c] * scale;                  break;
        case 1:  v = Wk_l[row * ND + c];                          break;
        case 2:  v = Wtop[row * ND + c] + Wbot[row * ND + c];     break;
        default: v = Wbot[row * ND + c];                          break;
    }
    Wcat[(size_t)l * ND * NCAT + idx] = v;
}

// ---------------- tiled SGEMM: C = act(A@W + bias) [+ resid] --------------------
// A: MxK row-major, W: KxN row-major. Tile TMx64x16, 128 threads.
template<int TM, bool GELU, bool BIAS, bool RES>
__global__ void gemm_k(const float* __restrict__ A, const float* __restrict__ W,
                       const float* __restrict__ bias,
                       const float* __restrict__ resid, float* __restrict__ C,
                       int N, int K, int CSTRIDE)
{
    __shared__ float As[16][TM];
    __shared__ float Bs[16][64];
    constexpr int R = TM / 8;                  // rows per thread (8 or 4)
    const int t  = threadIdx.x;
    const int bm = blockIdx.x * TM;
    const int bn = blockIdx.y * 64;
    const int ty = t >> 4;                     // 0..7
    const int tx = t & 15;                     // 0..15

    float acc[R][4];
#pragma unroll
    for (int i = 0; i < R; i++)
#pragma unroll
        for (int j = 0; j < 4; j++) acc[i][j] = 0.f;

    for (int k0 = 0; k0 < K; k0 += 16) {
#pragma unroll
        for (int rep = 0; rep < TM / 32; rep++) {
            int idx = t + rep * 128;
            int am  = idx >> 2;
            int ak  = (idx & 3) << 2;
            float4 av = *(const float4*)(A + (size_t)(bm + am) * K + k0 + ak);
            As[ak + 0][am] = av.x; As[ak + 1][am] = av.y;
            As[ak + 2][am] = av.z; As[ak + 3][am] = av.w;
        }
#pragma unroll
        for (int rep = 0; rep < 2; rep++) {
            int idx = t + rep * 128;
            int bk  = idx >> 4;
            int bn4 = (idx & 15) << 2;
            float4 bv = *(const float4*)(W + (size_t)(k0 + bk) * N + bn + bn4);
            *(float4*)&Bs[bk][bn4] = bv;
        }
        __syncthreads();
#pragma unroll
        for (int kk = 0; kk < 16; kk++) {
            float a[R], b[4];
#pragma unroll
            for (int i = 0; i < R; i += 4)
                *(float4*)&a[i] = *(const float4*)&As[kk][ty * R + i];
            *(float4*)&b[0] = *(const float4*)&Bs[kk][tx * 4];
#pragma unroll
            for (int i = 0; i < R; i++)
#pragma unroll
                for (int j = 0; j < 4; j++) acc[i][j] += a[i] * b[j];
        }
        __syncthreads();
    }
#pragma unroll
    for (int i = 0; i < R; i++) {
        int row = bm + ty * R + i;
        int col = bn + tx * 4;
        float vv[4];
#pragma unroll
        for (int j = 0; j < 4; j++) {
            float v = acc[i][j];
            if (BIAS) v += bias[col + j];
            if (GELU) v = gelu_fast(v);
            vv[j] = v;
        }
        if (RES) {
            float4 r4 = *(const float4*)(resid + (size_t)row * CSTRIDE + col);
            vv[0] += r4.x; vv[1] += r4.y; vv[2] += r4.z; vv[3] += r4.w;
        }
        float4 o; o.x = vv[0]; o.y = vv[1]; o.z = vv[2]; o.w = vv[3];
        *(float4*)(C + (size_t)row * CSTRIDE + col) = o;
    }
}

// ---------------- fused attention + weighted-gelu-sum: 2 CTAs per batch ---------
// qkpq rows have stride NCAT: [q | k | P | Q]
// CTA (b, ci) handles i-rows [ci*32, ci*32+32); needs all 64 k/Q rows.
__global__ void attn_u_kernel(const float* __restrict__ qkpq,
                              const float* __restrict__ bv1, float* __restrict__ u)
{
    extern __shared__ float sm[];
    float* sq = sm;                   // 32 rows
    float* sk = sq + 32 * SPITCH;     // 64 rows
    float* sP = sk + 64 * SPITCH;     // 32 rows
    float* sQ = sP + 32 * SPITCH;     // 64 rows
    float* sa = sQ + 64 * SPITCH;     // 32*64 logits/attn

    const int t  = threadIdx.x;       // 512 threads
    const int b  = blockIdx.x >> 1;
    const int r0 = (blockIdx.x & 1) * 32;
    const size_t base = (size_t)b * NKE;

    // load tiles into padded smem
    {
        for (int idx = t; idx < 32 * ND / 4; idx += 512) {
            int row = idx >> 5;              // 32 float4 per row
            int col = (idx & 31) << 2;
            const float* src = qkpq + (base + r0 + row) * NCAT + col;
            *(float4*)&sq[row * SPITCH + col] = *(const float4*)(src);            // q
            *(float4*)&sP[row * SPITCH + col] = *(const float4*)(src + 2 * ND);   // P
        }
        for (int idx = t; idx < 64 * ND / 4; idx += 512) {
            int row = idx >> 5;
            int col = (idx & 31) << 2;
            const float* src = qkpq + (base + row) * NCAT + col;
            *(float4*)&sk[row * SPITCH + col] = *(const float4*)(src + ND);       // k
            *(float4*)&sQ[row * SPITCH + col] = *(const float4*)(src + 3 * ND);   // Q
        }
    }
    __syncthreads();

    // logits: thread t computes 4 logits for local row i = t>>4, j = (t&15) + jj*16
    {
        const int i  = t >> 4;
        const int jb = t & 15;
        float acc[4] = {0, 0, 0, 0};
        const float* qrow = sq + i * SPITCH;
        for (int d = 0; d < ND; d += 4) {
            float4 qv = *(const float4*)(qrow + d);
#pragma unroll
            for (int jj = 0; jj < 4; jj++) {
                float4 kv = *(const float4*)(sk + (jb + jj * 16) * SPITCH + d);
                acc[jj] += qv.x * kv.x + qv.y * kv.y + qv.z * kv.z + qv.w * kv.w;
            }
        }
#pragma unroll
        for (int jj = 0; jj < 4; jj++) sa[i * 64 + jb + jj * 16] = acc[jj];
    }
    __syncthreads();

    // softmax over j: warp w handles local rows w*2, w*2+1
    {
        const int w = t >> 5, lane = t & 31;
#pragma unroll
        for (int r = 0; r < 2; r++) {
            int i = w * 2 + r;
            float v0 = sa[i * 64 + lane], v1 = sa[i * 64 + lane + 32];
            float mx = fmaxf(v0, v1);
            for (int o = 16; o; o >>= 1) mx = fmaxf(mx, __shfl_xor_sync(0xffffffffu, mx, o));
            float e0 = __expf(v0 - mx), e1 = __expf(v1 - mx);
            float s = e0 + e1;
            for (int o = 16; o; o >>= 1) s += __shfl_xor_sync(0xffffffffu, s, o);
            float inv = 1.0f / s;
            sa[i * 64 + lane] = e0 * inv;
            sa[i * 64 + lane + 32] = e1 * inv;
        }
    }
    __syncthreads();

    // u: warp w, lane covers d = lane*4..+3; local rows i = w + ii*16
    {
        const int w = t >> 5, lane = t & 31;
        const int dl = lane << 2;
        float4 bv = *(const float4*)(bv1 + dl);
#pragma unroll
        for (int ii = 0; ii < 2; ii++) {
            int i = w + ii * 16;
            float4 p = *(const float4*)(sP + i * SPITCH + dl);
            float p0 = p.x + bv.x, p1 = p.y + bv.y, p2 = p.z + bv.z, p3 = p.w + bv.w;
            float a0 = 0, a1 = 0, a2 = 0, a3 = 0;
            for (int j = 0; j < NKE; j += 4) {
                float4 att = *(const float4*)&sa[i * 64 + j];
#pragma unroll
                for (int jj = 0; jj < 4; jj++) {
                    float aw = (jj == 0) ? att.x : (jj == 1) ? att.y : (jj == 2) ? att.z : att.w;
                    float4 qq = *(const float4*)(sQ + (j + jj) * SPITCH + dl);
                    a0 += aw * gelu_fast(p0 - qq.x);
                    a1 += aw * gelu_fast(p1 - qq.y);
                    a2 += aw * gelu_fast(p2 - qq.z);
                    a3 += aw * gelu_fast(p3 - qq.w);
                }
            }
            float4 o; o.x = a0; o.y = a1; o.z = a2; o.w = a3;
            *(float4*)(u + (base + r0 + i) * ND + dl) = o;
        }
    }
}

// ---------------- layernorm (warp per row of 128) -------------------------------
__global__ void ln_kernel(const float* __restrict__ in, const float* __restrict__ g,
                          const float* __restrict__ bta, float* __restrict__ out)
{
    int row  = blockIdx.x * 8 + (threadIdx.x >> 5);
    int lane = threadIdx.x & 31;
    const float4 v = *(const float4*)(in + (size_t)row * ND + lane * 4);
    float s  = v.x + v.y + v.z + v.w;
    float s2 = v.x * v.x + v.y * v.y + v.z * v.z + v.w * v.w;
    for (int o = 16; o; o >>= 1) {
        s  += __shfl_xor_sync(0xffffffffu, s, o);
        s2 += __shfl_xor_sync(0xffffffffu, s2, o);
    }
    float mu  = s * (1.0f / ND);
    float var = s2 * (1.0f / ND) - mu * mu;
    float inv = rsqrtf(var + 1e-5f);
    float4 gg = *(const float4*)(g + lane * 4);
    float4 bb = *(const float4*)(bta + lane * 4);
    float4 o;
    o.x = (v.x - mu) * inv * gg.x + bb.x;
    o.y = (v.y - mu) * inv * gg.y + bb.y;
    o.z = (v.z - mu) * inv * gg.z + bb.z;
    o.w = (v.w - mu) * inv * gg.w + bb.w;
    *(float4*)(out + (size_t)row * ND + lane * 4) = o;
}

// ---------------- fused head: pool + proj(gelu) + mu/sp projections -------------
__global__ void head_kernel(const float* __restrict__ x,
                            const float* __restrict__ Wp,  const float* __restrict__ bp,
                            const float* __restrict__ Wmu, const float* __restrict__ bmu,
                            const float* __restrict__ Wsp, const float* __restrict__ bsp,
                            float* __restrict__ out)
{
    __shared__ float spool[ND];
    __shared__ float sproj[NS];
    const int b = blockIdx.x;
    const int t = threadIdx.x;   // 128 threads

    // pool over entities
    {
        float s = 0.f;
        const float* p = x + (size_t)b * NKE * ND + t;
        for (int i = 0; i < NKE; i++) s += p[i * ND];
        spool[t] = s;
    }
    __syncthreads();

    // proj = gelu(pooled @ Wp + bp)
    {
        float acc = bp[t];
        for (int d = 0; d < ND; d++) acc += spool[d] * Wp[d * NS + t];
        sproj[t] = gelu_fast(acc);
    }
    __syncthreads();

    // mu/sp
    {
        float amu = bmu[t], asp = bsp[t];
        for (int s = 0; s < NS; s++) {
            float f = sproj[s];
            amu += f * Wmu[s * NS + t];
            asp += f * Wsp[s * NS + t];
        }
        out[(size_t)b * NS + t] = amu;
        out[(size_t)NB * NS + (size_t)b * NS + t] = asp;
    }
}

// ---------------- launch --------------------------------------------------------
extern "C" void kernel_launch(void* const* d_in, const int* in_sizes, int n_in,
                              void* d_out, int out_size)
{
    const float* x_in = (const float*)d_in[0];
    const float* Wk   = (const float*)d_in[1];
    const float* Wq   = (const float*)d_in[2];
    const float* Wv1  = (const float*)d_in[3];
    const float* bv1  = (const float*)d_in[4];
    const float* Wv2  = (const float*)d_in[5];
    const float* bv2  = (const float*)d_in[6];
    const float* lng  = (const float*)d_in[7];
    const float* lnb  = (const float*)d_in[8];
    const float* Wm1  = (const float*)d_in[9];
    const float* bm1  = (const float*)d_in[10];
    const float* Wm2  = (const float*)d_in[11];
    const float* bm2  = (const float*)d_in[12];
    const float* Wp   = (const float*)d_in[13];
    const float* bp   = (const float*)d_in[14];
    const float* Wmu  = (const float*)d_in[15];
    const float* bmu  = (const float*)d_in[16];
    const float* Wsp  = (const float*)d_in[17];
    const float* bsp  = (const float*)d_in[18];
    float* out = (float*)d_out;

    float *px, *pqkpq, *pu, *ph2, *pln, *pm, *pwcat;
    cudaGetSymbolAddress((void**)&px,    g_x);
    cudaGetSymbolAddress((void**)&pqkpq, g_qkpq);
    cudaGetSymbolAddress((void**)&pu,    g_u);
    cudaGetSymbolAddress((void**)&ph2,   g_h2);
    cudaGetSymbolAddress((void**)&pln,   g_ln);
    cudaGetSymbolAddress((void**)&pm,    g_mm);
    cudaGetSymbolAddress((void**)&pwcat, g_wcat);

    const int SMEM_AU = (192 * SPITCH + 32 * NKE) * (int)sizeof(float);   // ~107KB
    cudaFuncSetAttribute(attn_u_kernel, cudaFuncAttributeMaxDynamicSharedMemorySize, SMEM_AU);

    const float scale = 1.0f / sqrtf((float)ND);

    prep_wcat<<<dim3(256, NL), 256>>>(Wq, Wk, Wv1, pwcat, scale);

    dim3 gcat(MROWS / 64, NCAT / 64);   // (128, 8) = 1024 CTAs
    dim3 g32(MROWS / 32, ND / 64);      // (256, 2) = 512 CTAs
    for (int l = 0; l < NL; l++) {
        const float* Wcat_l = pwcat + (size_t)l * ND * NCAT;
        const float* bv1_l = bv1 + (size_t)l * ND;
        const float* Wv2_l = Wv2 + (size_t)l * ND * ND;
        const float* bv2_l = bv2 + (size_t)l * ND;
        const float* g_l   = lng + (size_t)l * ND;
        const float* b_l   = lnb + (size_t)l * ND;
        const float* Wm1_l = Wm1 + (size_t)l * ND * ND;
        const float* bm1_l = bm1 + (size_t)l * ND;
        const float* Wm2_l = Wm2 + (size_t)l * ND * ND;
        const float* bm2_l = bm2 + (size_t)l * ND;

        const float* xa = (l == 0) ? x_in : px;   // current x (read-only this layer)

        // [q|k|P|Q] = x @ Wcat
        gemm_k<64, false, false, false><<<gcat, 128>>>(xa, Wcat_l, nullptr, nullptr, pqkpq, NCAT, ND, NCAT);

        attn_u_kernel<<<NB * 2, 512, SMEM_AU>>>(pqkpq, bv1_l, pu);

        // h2 = x + u@Wv2 + bv2
        gemm_k<32, false, true, true><<<g32, 128>>>(pu, Wv2_l, bv2_l, xa, ph2, ND, ND, ND);
        // mlp_in = LN(h2)
        ln_kernel<<<MROWS / 8, 256>>>(ph2, g_l, b_l, pln);
        // m = gelu(mlp_in@Wm1 + bm1)
        gemm_k<32, true, true, false><<<g32, 128>>>(pln, Wm1_l, bm1_l, nullptr, pm, ND, ND, ND);
        // x = x + m@Wm2 + bm2
        gemm_k<32, false, true, true><<<g32, 128>>>(pm, Wm2_l, bm2_l, xa, px, ND, ND, ND);
    }

    head_kernel<<<NB, ND>>>(px, Wp, bp, Wmu, bmu, Wsp, bsp, out);
}

// round 5
// speedup vs baseline: 1.7856x; 1.0932x over previous
#include <cuda_runtime.h>
#include <cmath>

#define NB 128   // batch
#define NKE 64   // entities (K)
#define ND 128   // feature dim D
#define NS 128   // S
#define NL 2     // layers
#define MROWS (NB*NKE)   // 8192
#define SPITCH 132       // padded smem row stride (floats) for attn tiles
#define NCAT 512         // fused q|k|P|Q width
#define UTP 36           // transposed-tile row stride (floats), 32 + 4 pad

// ---------------- scratch (static device arrays; no allocation) ----------------
__device__ float g_x[MROWS*ND];
__device__ float g_qkpq[MROWS*NCAT];          // 16 MB
__device__ float g_u[MROWS*ND];
__device__ float g_wcat[NL*ND*NCAT];          // per-layer fused weights

__device__ __forceinline__ float gelu_fast(float x) {
    // gelu(x) = 0.5*x*(1 + erf(x/sqrt(2))), erf via A&S 7.1.25 (|err| <= 2.5e-5)
    float z = fabsf(x) * 0.70710678118654752f;
    float t = __frcp_rn(fmaf(0.47047f, z, 1.0f));
    float p = fmaf(fmaf(0.7478556f, t, -0.0958798f), t, 0.3480242f) * t;
    float e = __expf(-z * z);
    float erfv = fmaf(-p, e, 1.0f);
    float s = copysignf(erfv, x);
    float hx = 0.5f * x;
    return fmaf(hx, s, hx);
}

// ---------------- weight-prep: Wcat[l] = [Wq*scale | Wk | Wtop+Wbot | Wbot] ------
__global__ void prep_wcat(const float* __restrict__ Wq, const float* __restrict__ Wk,
                          const float* __restrict__ Wv1, float* __restrict__ Wcat,
                          float scale)
{
    int l   = blockIdx.y;
    int idx = blockIdx.x * 256 + threadIdx.x;      // 0..65535
    int row = idx >> 9;                             // 0..127
    int col = idx & 511;
    int c   = col & 127;
    const float* Wq_l  = Wq  + (size_t)l * ND * ND;
    const float* Wk_l  = Wk  + (size_t)l * ND * ND;
    const float* Wtop  = Wv1 + (size_t)l * 2 * ND * ND;
    const float* Wbot  = Wtop + (size_t)ND * ND;
    float v;
    switch (col >> 7) {
        case 0:  v = Wq_l[row * ND + c] * scale;                  break;
        case 1:  v = Wk_l[row * ND + c];                          break;
        case 2:  v = Wtop[row * ND + c] + Wbot[row * ND + c];     break;
        default: v = Wbot[row * ND + c];                          break;
    }
    Wcat[(size_t)l * ND * NCAT + idx] = v;
}

// ---------------- qkpq GEMM: C[8192,512] = A[8192,128] @ W[128,512] --------------
// Tile 64x128x16, 256 threads, double-buffered smem + register prefetch.
__global__ __launch_bounds__(256) void gemm_qkpq(const float* __restrict__ A,
                                                 const float* __restrict__ W,
                                                 float* __restrict__ C)
{
    __shared__ float As[2][16 * 64];
    __shared__ float Bs[2][16 * 128];
    const int t    = threadIdx.x;
    const int bm   = blockIdx.x * 64;
    const int bn   = blockIdx.y * 128;
    const int ty   = t >> 5;          // warp 0..7 -> rows ty*8..+7
    const int lane = t & 31;          // cols lane*4..+3

    const int am  = t >> 2;           // A-load: row 0..63
    const int ak4 = (t & 3) << 2;     // A-load: k 0,4,8,12
    const int bk  = t >> 5;           // B-load: k-row 0..7 (+8 for rep1)
    const int bn4 = (t & 31) << 2;    // B-load: col group

    float acc[8][4];
#pragma unroll
    for (int i = 0; i < 8; i++)
#pragma unroll
        for (int j = 0; j < 4; j++) acc[i][j] = 0.f;

    // prologue: chunk 0 -> buffer 0
    {
        float4 av = *(const float4*)(A + (size_t)(bm + am) * ND + ak4);
        As[0][(ak4 + 0) * 64 + am] = av.x;
        As[0][(ak4 + 1) * 64 + am] = av.y;
        As[0][(ak4 + 2) * 64 + am] = av.z;
        As[0][(ak4 + 3) * 64 + am] = av.w;
        *(float4*)&Bs[0][bk * 128 + bn4]       = *(const float4*)(W + (size_t)bk * NCAT + bn + bn4);
        *(float4*)&Bs[0][(bk + 8) * 128 + bn4] = *(const float4*)(W + (size_t)(bk + 8) * NCAT + bn + bn4);
    }
    __syncthreads();

    for (int c = 0; c < 8; c++) {
        const int cb = c & 1;
        float4 pa, pb0, pb1;
        if (c < 7) {
            int k0n = (c + 1) * 16;
            pa  = *(const float4*)(A + (size_t)(bm + am) * ND + k0n + ak4);
            pb0 = *(const float4*)(W + (size_t)(k0n + bk) * NCAT + bn + bn4);
            pb1 = *(const float4*)(W + (size_t)(k0n + bk + 8) * NCAT + bn + bn4);
        }
        const float* Ab = As[cb];
        const float* Bb = Bs[cb];
#pragma unroll
        for (int kk = 0; kk < 16; kk++) {
            float a[8], b[4];
            *(float4*)&a[0] = *(const float4*)&Ab[kk * 64 + ty * 8];
            *(float4*)&a[4] = *(const float4*)&Ab[kk * 64 + ty * 8 + 4];
            *(float4*)&b[0] = *(const float4*)&Bb[kk * 128 + lane * 4];
#pragma unroll
            for (int i = 0; i < 8; i++)
#pragma unroll
                for (int j = 0; j < 4; j++) acc[i][j] = fmaf(a[i], b[j], acc[i][j]);
        }
        __syncthreads();
        if (c < 7) {
            const int nb = cb ^ 1;
            As[nb][(ak4 + 0) * 64 + am] = pa.x;
            As[nb][(ak4 + 1) * 64 + am] = pa.y;
            As[nb][(ak4 + 2) * 64 + am] = pa.z;
            As[nb][(ak4 + 3) * 64 + am] = pa.w;
            *(float4*)&Bs[nb][bk * 128 + bn4]       = pb0;
            *(float4*)&Bs[nb][(bk + 8) * 128 + bn4] = pb1;
            __syncthreads();
        }
    }

#pragma unroll
    for (int i = 0; i < 8; i++) {
        float4 o; o.x = acc[i][0]; o.y = acc[i][1]; o.z = acc[i][2]; o.w = acc[i][3];
        *(float4*)(C + (size_t)(bm + ty * 8 + i) * NCAT + bn + lane * 4) = o;
    }
}

// ---------------- fused attention + weighted-gelu-sum: 2 CTAs per batch ---------
__global__ void attn_u_kernel(const float* __restrict__ qkpq,
                              const float* __restrict__ bv1, float* __restrict__ u)
{
    extern __shared__ float sm[];
    float* sq = sm;                   // 32 rows
    float* sk = sq + 32 * SPITCH;     // 64 rows
    float* sP = sk + 64 * SPITCH;     // 32 rows
    float* sQ = sP + 32 * SPITCH;     // 64 rows
    float* sa = sQ + 64 * SPITCH;     // 32*64 logits/attn

    const int t  = threadIdx.x;       // 512 threads
    const int b  = blockIdx.x >> 1;
    const int r0 = (blockIdx.x & 1) * 32;
    const size_t base = (size_t)b * NKE;

    {
        for (int idx = t; idx < 32 * ND / 4; idx += 512) {
            int row = idx >> 5;
            int col = (idx & 31) << 2;
            const float* src = qkpq + (base + r0 + row) * NCAT + col;
            *(float4*)&sq[row * SPITCH + col] = *(const float4*)(src);            // q
            *(float4*)&sP[row * SPITCH + col] = *(const float4*)(src + 2 * ND);   // P
        }
        for (int idx = t; idx < 64 * ND / 4; idx += 512) {
            int row = idx >> 5;
            int col = (idx & 31) << 2;
            const float* src = qkpq + (base + row) * NCAT + col;
            *(float4*)&sk[row * SPITCH + col] = *(const float4*)(src + ND);       // k
            *(float4*)&sQ[row * SPITCH + col] = *(const float4*)(src + 3 * ND);   // Q
        }
    }
    __syncthreads();

    // logits
    {
        const int i  = t >> 4;
        const int jb = t & 15;
        float acc[4] = {0, 0, 0, 0};
        const float* qrow = sq + i * SPITCH;
        for (int d = 0; d < ND; d += 4) {
            float4 qv = *(const float4*)(qrow + d);
#pragma unroll
            for (int jj = 0; jj < 4; jj++) {
                float4 kv = *(const float4*)(sk + (jb + jj * 16) * SPITCH + d);
                acc[jj] += qv.x * kv.x + qv.y * kv.y + qv.z * kv.z + qv.w * kv.w;
            }
        }
#pragma unroll
        for (int jj = 0; jj < 4; jj++) sa[i * 64 + jb + jj * 16] = acc[jj];
    }
    __syncthreads();

    // softmax
    {
        const int w = t >> 5, lane = t & 31;
#pragma unroll
        for (int r = 0; r < 2; r++) {
            int i = w * 2 + r;
            float v0 = sa[i * 64 + lane], v1 = sa[i * 64 + lane + 32];
            float mx = fmaxf(v0, v1);
            for (int o = 16; o; o >>= 1) mx = fmaxf(mx, __shfl_xor_sync(0xffffffffu, mx, o));
            float e0 = __expf(v0 - mx), e1 = __expf(v1 - mx);
            float s = e0 + e1;
            for (int o = 16; o; o >>= 1) s += __shfl_xor_sync(0xffffffffu, s, o);
            float inv = 1.0f / s;
            sa[i * 64 + lane] = e0 * inv;
            sa[i * 64 + lane + 32] = e1 * inv;
        }
    }
    __syncthreads();

    // u accumulate
    {
        const int w = t >> 5, lane = t & 31;
        const int dl = lane << 2;
        float4 bv = *(const float4*)(bv1 + dl);
#pragma unroll
        for (int ii = 0; ii < 2; ii++) {
            int i = w + ii * 16;
            float4 p = *(const float4*)(sP + i * SPITCH + dl);
            float p0 = p.x + bv.x, p1 = p.y + bv.y, p2 = p.z + bv.z, p3 = p.w + bv.w;
            float a0 = 0, a1 = 0, a2 = 0, a3 = 0;
            for (int j = 0; j < NKE; j += 4) {
                float4 att = *(const float4*)&sa[i * 64 + j];
#pragma unroll
                for (int jj = 0; jj < 4; jj++) {
                    float aw = (jj == 0) ? att.x : (jj == 1) ? att.y : (jj == 2) ? att.z : att.w;
                    float4 qq = *(const float4*)(sQ + (j + jj) * SPITCH + dl);
                    a0 += aw * gelu_fast(p0 - qq.x);
                    a1 += aw * gelu_fast(p1 - qq.y);
                    a2 += aw * gelu_fast(p2 - qq.z);
                    a3 += aw * gelu_fast(p3 - qq.w);
                }
            }
            float4 o; o.x = a0; o.y = a1; o.z = a2; o.w = a3;
            *(float4*)(u + (base + r0 + i) * ND + dl) = o;
        }
    }
}

// ---------------- fused post-attention chain ------------------------------------
// One CTA = 32 rows. smem: uT(transposed A) / xs / hs / Ws(double buffer).
// h2 = x + u@Wv2 + bv2; ln; t = gelu(ln@Wm1+bm1); out = x + t@Wm2 + bm2.
__device__ __forceinline__ void tile_gemm32(const float* __restrict__ Wg, float* __restrict__ Ws,
                                            const float* __restrict__ uT,
                                            int ty, int lane, int t, float acc[4][4])
{
    const int bk  = t >> 5;
    const int bn4 = (t & 31) << 2;
    // prologue: chunk0 -> buf0
    *(float4*)&Ws[bk * 128 + bn4]       = *(const float4*)(Wg + (size_t)bk * ND + bn4);
    *(float4*)&Ws[(bk + 8) * 128 + bn4] = *(const float4*)(Wg + (size_t)(bk + 8) * ND + bn4);
    __syncthreads();
    for (int c = 0; c < 8; c++) {
        const int cb = c & 1;
        float4 pb0, pb1;
        if (c < 7) {
            int k0n = (c + 1) * 16;
            pb0 = *(const float4*)(Wg + (size_t)(k0n + bk) * ND + bn4);
            pb1 = *(const float4*)(Wg + (size_t)(k0n + bk + 8) * ND + bn4);
        }
        const float* Wb = Ws + cb * 2048;
        const int k0 = c * 16;
#pragma unroll
        for (int kk = 0; kk < 16; kk++) {
            float a[4], b[4];
            *(float4*)&a[0] = *(const float4*)&uT[(k0 + kk) * UTP + ty * 4];
            *(float4*)&b[0] = *(const float4*)&Wb[kk * 128 + lane * 4];
#pragma unroll
            for (int i = 0; i < 4; i++)
#pragma unroll
                for (int j = 0; j < 4; j++) acc[i][j] = fmaf(a[i], b[j], acc[i][j]);
        }
        __syncthreads();
        if (c < 7) {
            float* Wn = Ws + (cb ^ 1) * 2048;
            *(float4*)&Wn[bk * 128 + bn4]       = pb0;
            *(float4*)&Wn[(bk + 8) * 128 + bn4] = pb1;
            __syncthreads();
        }
    }
}

__global__ __launch_bounds__(256) void fused_mlp(
    const float* __restrict__ u,   const float* __restrict__ xa,
    const float* __restrict__ Wv2, const float* __restrict__ bv2,
    const float* __restrict__ lng, const float* __restrict__ lnb,
    const float* __restrict__ Wm1, const float* __restrict__ bm1,
    const float* __restrict__ Wm2, const float* __restrict__ bm2,
    float* __restrict__ xo)
{
    extern __shared__ float sm[];
    float* uT = sm;                 // 128 * UTP = 4608
    float* xs = uT + 128 * UTP;     // 32 * 128  = 4096
    float* hs = xs + 32 * 128;      // 4096
    float* Ws = hs + 32 * 128;      // 2 * 2048  = 4096

    const int t    = threadIdx.x;   // 256
    const int r0   = blockIdx.x * 32;
    const int ty   = t >> 5;        // rows ty*4..+3
    const int lane = t & 31;        // cols lane*4..+3
    const int cl   = lane << 2;

    // stage u transposed + x row-major
    for (int idx = t; idx < 32 * ND; idx += 256) {
        int r = idx >> 7, k = idx & 127;
        uT[k * UTP + r] = u[(size_t)(r0 + r) * ND + k];
    }
    for (int idx = t; idx < 32 * 32; idx += 256) {
        int r = idx >> 5, c4 = (idx & 31) << 2;
        *(float4*)&xs[r * 128 + c4] = *(const float4*)(xa + (size_t)(r0 + r) * ND + c4);
    }
    __syncthreads();

    float acc[4][4];
    // ---- GEMM1: h2 = u@Wv2 + bv2 + x -> hs
#pragma unroll
    for (int i = 0; i < 4; i++)
#pragma unroll
        for (int j = 0; j < 4; j++) acc[i][j] = 0.f;
    tile_gemm32(Wv2, Ws, uT, ty, lane, t, acc);
    {
        float4 bb = *(const float4*)(bv2 + cl);
#pragma unroll
        for (int i = 0; i < 4; i++) {
            int r = ty * 4 + i;
            float4 xv = *(const float4*)&xs[r * 128 + cl];
            float4 o;
            o.x = acc[i][0] + bb.x + xv.x;
            o.y = acc[i][1] + bb.y + xv.y;
            o.z = acc[i][2] + bb.z + xv.z;
            o.w = acc[i][3] + bb.w + xv.w;
            *(float4*)&hs[r * 128 + cl] = o;
        }
    }
    __syncthreads();

    // ---- LayerNorm rows of hs (warp ty handles rows ty*4..+3)
    {
        float4 gg = *(const float4*)(lng + cl);
        float4 bb = *(const float4*)(lnb + cl);
#pragma unroll
        for (int i = 0; i < 4; i++) {
            int r = ty * 4 + i;
            float4 v = *(const float4*)&hs[r * 128 + cl];
            float s  = v.x + v.y + v.z + v.w;
            float s2 = v.x * v.x + v.y * v.y + v.z * v.z + v.w * v.w;
            for (int o = 16; o; o >>= 1) {
                s  += __shfl_xor_sync(0xffffffffu, s, o);
                s2 += __shfl_xor_sync(0xffffffffu, s2, o);
            }
            float mu  = s * (1.0f / ND);
            float var = s2 * (1.0f / ND) - mu * mu;
            float inv = rsqrtf(var + 1e-5f);
            float4 o;
            o.x = (v.x - mu) * inv * gg.x + bb.x;
            o.y = (v.y - mu) * inv * gg.y + bb.y;
            o.z = (v.z - mu) * inv * gg.z + bb.z;
            o.w = (v.w - mu) * inv * gg.w + bb.w;
            *(float4*)&hs[r * 128 + cl] = o;
        }
    }
    __syncthreads();

    // ---- transpose hs -> uT
    for (int idx = t; idx < 32 * ND; idx += 256) {
        int r = idx >> 7, k = idx & 127;
        uT[k * UTP + r] = hs[r * 128 + k];
    }
    __syncthreads();

    // ---- GEMM2: t = gelu(ln@Wm1 + bm1) -> hs
#pragma unroll
    for (int i = 0; i < 4; i++)
#pragma unroll
        for (int j = 0; j < 4; j++) acc[i][j] = 0.f;
    tile_gemm32(Wm1, Ws, uT, ty, lane, t, acc);
    {
        float4 bb = *(const float4*)(bm1 + cl);
#pragma unroll
        for (int i = 0; i < 4; i++) {
            int r = ty * 4 + i;
            float4 o;
            o.x = gelu_fast(acc[i][0] + bb.x);
            o.y = gelu_fast(acc[i][1] + bb.y);
            o.z = gelu_fast(acc[i][2] + bb.z);
            o.w = gelu_fast(acc[i][3] + bb.w);
            *(float4*)&hs[r * 128 + cl] = o;
        }
    }
    __syncthreads();

    // ---- transpose hs -> uT
    for (int idx = t; idx < 32 * ND; idx += 256) {
        int r = idx >> 7, k = idx & 127;
        uT[k * UTP + r] = hs[r * 128 + k];
    }
    __syncthreads();

    // ---- GEMM3: out = x + t@Wm2 + bm2 -> global
#pragma unroll
    for (int i = 0; i < 4; i++)
#pragma unroll
        for (int j = 0; j < 4; j++) acc[i][j] = 0.f;
    tile_gemm32(Wm2, Ws, uT, ty, lane, t, acc);
    {
        float4 bb = *(const float4*)(bm2 + cl);
#pragma unroll
        for (int i = 0; i < 4; i++) {
            int r = ty * 4 + i;
            float4 xv = *(const float4*)&xs[r * 128 + cl];
            float4 o;
            o.x = acc[i][0] + bb.x + xv.x;
            o.y = acc[i][1] + bb.y + xv.y;
            o.z = acc[i][2] + bb.z + xv.z;
            o.w = acc[i][3] + bb.w + xv.w;
            *(float4*)(xo + (size_t)(r0 + r) * ND + cl) = o;
        }
    }
}

// ---------------- fused head: pool + proj(gelu) + mu/sp projections -------------
__global__ void head_kernel(const float* __restrict__ x,
                            const float* __restrict__ Wp,  const float* __restrict__ bp,
                            const float* __restrict__ Wmu, const float* __restrict__ bmu,
                            const float* __restrict__ Wsp, const float* __restrict__ bsp,
                            float* __restrict__ out)
{
    __shared__ float spool[ND];
    __shared__ float sproj[NS];
    const int b = blockIdx.x;
    const int t = threadIdx.x;   // 128 threads

    {
        float s = 0.f;
        const float* p = x + (size_t)b * NKE * ND + t;
        for (int i = 0; i < NKE; i++) s += p[i * ND];
        spool[t] = s;
    }
    __syncthreads();
    {
        float acc = bp[t];
        for (int d = 0; d < ND; d++) acc += spool[d] * Wp[d * NS + t];
        sproj[t] = gelu_fast(acc);
    }
    __syncthreads();
    {
        float amu = bmu[t], asp = bsp[t];
        for (int s = 0; s < NS; s++) {
            float f = sproj[s];
            amu += f * Wmu[s * NS + t];
            asp += f * Wsp[s * NS + t];
        }
        out[(size_t)b * NS + t] = amu;
        out[(size_t)NB * NS + (size_t)b * NS + t] = asp;
    }
}

// ---------------- launch --------------------------------------------------------
extern "C" void kernel_launch(void* const* d_in, const int* in_sizes, int n_in,
                              void* d_out, int out_size)
{
    const float* x_in = (const float*)d_in[0];
    const float* Wk   = (const float*)d_in[1];
    const float* Wq   = (const float*)d_in[2];
    const float* Wv1  = (const float*)d_in[3];
    const float* bv1  = (const float*)d_in[4];
    const float* Wv2  = (const float*)d_in[5];
    const float* bv2  = (const float*)d_in[6];
    const float* lng  = (const float*)d_in[7];
    const float* lnb  = (const float*)d_in[8];
    const float* Wm1  = (const float*)d_in[9];
    const float* bm1  = (const float*)d_in[10];
    const float* Wm2  = (const float*)d_in[11];
    const float* bm2  = (const float*)d_in[12];
    const float* Wp   = (const float*)d_in[13];
    const float* bp   = (const float*)d_in[14];
    const float* Wmu  = (const float*)d_in[15];
    const float* bmu  = (const float*)d_in[16];
    const float* Wsp  = (const float*)d_in[17];
    const float* bsp  = (const float*)d_in[18];
    float* out = (float*)d_out;

    float *px, *pqkpq, *pu, *pwcat;
    cudaGetSymbolAddress((void**)&px,    g_x);
    cudaGetSymbolAddress((void**)&pqkpq, g_qkpq);
    cudaGetSymbolAddress((void**)&pu,    g_u);
    cudaGetSymbolAddress((void**)&pwcat, g_wcat);

    const int SMEM_AU = (192 * SPITCH + 32 * NKE) * (int)sizeof(float);   // ~107KB
    cudaFuncSetAttribute(attn_u_kernel, cudaFuncAttributeMaxDynamicSharedMemorySize, SMEM_AU);
    const int SMEM_F = (128 * UTP + 3 * 32 * 128 + 2 * 2048) * (int)sizeof(float);  // ~66KB
    cudaFuncSetAttribute(fused_mlp, cudaFuncAttributeMaxDynamicSharedMemorySize, SMEM_F);

    const float scale = 1.0f / sqrtf((float)ND);

    prep_wcat<<<dim3(256, NL), 256>>>(Wq, Wk, Wv1, pwcat, scale);

    dim3 gq(MROWS / 64, NCAT / 128);    // (128, 4) = 512 CTAs
    for (int l = 0; l < NL; l++) {
        const float* Wcat_l = pwcat + (size_t)l * ND * NCAT;
        const float* bv1_l = bv1 + (size_t)l * ND;
        const float* Wv2_l = Wv2 + (size_t)l * ND * ND;
        const float* bv2_l = bv2 + (size_t)l * ND;
        const float* g_l   = lng + (size_t)l * ND;
        const float* b_l   = lnb + (size_t)l * ND;
        const float* Wm1_l = Wm1 + (size_t)l * ND * ND;
        const float* bm1_l = bm1 + (size_t)l * ND;
        const float* Wm2_l = Wm2 + (size_t)l * ND * ND;
        const float* bm2_l = bm2 + (size_t)l * ND;

        const float* xa = (l == 0) ? x_in : px;   // current x (read-only this layer)

        gemm_qkpq<<<gq, 256>>>(xa, Wcat_l, pqkpq);
        attn_u_kernel<<<NB * 2, 512, SMEM_AU>>>(pqkpq, bv1_l, pu);
        fused_mlp<<<MROWS / 32, 256, SMEM_F>>>(pu, xa, Wv2_l, bv2_l, g_l, b_l,
                                               Wm1_l, bm1_l, Wm2_l, bm2_l, px);
    }

    head_kernel<<<NB, ND>>>(px, Wp, bp, Wmu, bmu, Wsp, bsp, out);
}